// round 16
// baseline (speedup 1.0000x reference)
#include <cuda_runtime.h>
#include <cuda_fp16.h>
#include <cstdint>

// ============================================================================
// Fused MHA  b=32, s=1024, d_model=128, h=8, d_head=16 (fp32 in/out).
//   K0: prep_w -- Wqkv/Wo -> fp16 (once, tiny)
//   K1: qkv    -- plain-fp16 HMMA, double-buffered smem, 3 CTAs/SM;
//                 epilogue emits fp16 Q(xlog2e)/K, V transposed
//   K2: attn   -- fp16 HMMA flash; QK^T fp16 ACCUM -> ex2.f16x2 direct;
//                 HADD2 l-fold (2 ones-MMA/32keys); 64-key chunks (half syncs)
//   K3: proj   -- plain-fp16 HMMA, double-buffered smem, 3 CTAs/SM
// ============================================================================

#define DEV_INLINE __device__ __forceinline__

DEV_INLINE uint32_t f16x2(float hi, float lo) {
    uint32_t r;
    asm("cvt.rn.f16x2.f32 %0, %1, %2;" : "=r"(r) : "f"(hi), "f"(lo));
    return r;
}
DEV_INLINE uint32_t h2ex2(uint32_t x) {
    uint32_t y;
    asm("ex2.approx.f16x2 %0, %1;" : "=r"(y) : "r"(x));
    return y;
}
DEV_INLINE uint32_t hadd2u(uint32_t a, uint32_t b) {
    uint32_t y;
    asm("add.f16x2 %0, %1, %2;" : "=r"(y) : "r"(a), "r"(b));
    return y;
}
DEV_INLINE uint32_t smem_u32(const void* p) {
    return (uint32_t)__cvta_generic_to_shared(p);
}
DEV_INLINE void ldsm4(uint32_t* r, uint32_t addr) {
    asm volatile(
        "ldmatrix.sync.aligned.m8n8.x4.shared.b16 {%0,%1,%2,%3}, [%4];"
        : "=r"(r[0]), "=r"(r[1]), "=r"(r[2]), "=r"(r[3]) : "r"(addr));
}

// m16n8k16 fp16 HMMA, f32 accum
DEV_INLINE void mma16n8k16f16(float* d, const uint32_t* a, const uint32_t* b,
                              const float* c) {
    asm volatile(
        "mma.sync.aligned.m16n8k16.row.col.f32.f16.f16.f32 "
        "{%0,%1,%2,%3}, {%4,%5,%6,%7}, {%8,%9}, {%10,%11,%12,%13};"
        : "=f"(d[0]), "=f"(d[1]), "=f"(d[2]), "=f"(d[3])
        : "r"(a[0]), "r"(a[1]), "r"(a[2]), "r"(a[3]),
          "r"(b[0]), "r"(b[1]),
          "f"(c[0]), "f"(c[1]), "f"(c[2]), "f"(c[3]));
}
// m16n8k16 fp16 HMMA, fp16 accum, zero C (D = 2 packed f16x2 regs)
DEV_INLINE void mma16n8k16h_z(uint32_t* d, const uint32_t* a, const uint32_t* b) {
    asm volatile(
        "mma.sync.aligned.m16n8k16.row.col.f16.f16.f16.f16 "
        "{%0,%1}, {%2,%3,%4,%5}, {%6,%7}, {%8,%9};"
        : "=r"(d[0]), "=r"(d[1])
        : "r"(a[0]), "r"(a[1]), "r"(a[2]), "r"(a[3]),
          "r"(b[0]), "r"(b[1]), "r"(0u), "r"(0u));
}

static constexpr int B = 32;
static constexpr int S = 1024;
static constexpr int H = 8;
static constexpr int DH = 16;
static constexpr int DM = 128;
static constexpr int NQKV = 3 * DM;           // 384
static constexpr int NTOK = B * S;            // 32768
static constexpr size_t PER_T = (size_t)B * H * S * DH;  // 4194304
static constexpr int WQKV_N = NQKV * DM;      // 49152
static constexpr int WO_N = DM * DM;          // 16384
static constexpr float L2E = 1.4426950408889634f;

// Scratch (allocation-free rule: __device__ globals)
__device__ __half g_q16[PER_T];   // Q * log2(e), fp16, [bh][s][d]
__device__ __half g_k16[PER_T];   // K fp16, [bh][s][d]
__device__ __half g_v16[PER_T];   // V fp16 TRANSPOSED, [bh][d][s]
__device__ __half g_wh[WQKV_N + WO_N];  // Wqkv then Wo, fp16

// ============================================================================
// Kernel 0: convert weights to fp16 (once).
// ============================================================================
__global__ void prep_w(const float* __restrict__ Wqkv, const float* __restrict__ Wo)
{
    int i = blockIdx.x * 256 + threadIdx.x;
    if (i >= WQKV_N + WO_N) return;
    float w = (i < WQKV_N) ? Wqkv[i] : Wo[i - WQKV_N];
    g_wh[i] = __float2half(w);
}

// ============================================================================
// Kernel 1: QKV projection, plain-fp16 HMMA + ldmatrix, DOUBLE-BUFFERED,
// 3 CTAs/SM. Tile 128(M) x 64(N); warp tile 32x32.
// ============================================================================
__global__ void __launch_bounds__(256, 3) qkv_kernel(
    const float* __restrict__ x, const float* __restrict__ bias)
{
    __shared__ __align__(16) __half AsH[2][128 * 40];
    __shared__ __align__(16) __half BsH[2][64 * 40];
    const int tid = threadIdx.x;
    const int lane = tid & 31;
    const int wid = tid >> 5;
    const int g = lane >> 2, t = lane & 3;
    const int m = lane >> 3, r = lane & 7;
    const int wm = wid & 3;
    const int wn = wid >> 2;
    const int m0 = blockIdx.x * 128;
    const int n0 = blockIdx.y * 64;

    const uint32_t aLane = ((wm * 32 + (m & 1) * 8 + r) * 40 + (m >> 1) * 8) * 2;
    const uint32_t bLane = ((wn * 32 + (m >> 1) * 8 + r) * 40 + (m & 1) * 8) * 2;
    const uint32_t aHb0 = smem_u32(AsH[0]) + aLane;
    const uint32_t bHb0 = smem_u32(BsH[0]) + bLane;
    const uint32_t ABUF = 128 * 40 * 2;
    const uint32_t BBUF = 64 * 40 * 2;

    float acc[2][4][4];
#pragma unroll
    for (int mt = 0; mt < 2; mt++)
#pragma unroll
        for (int nt = 0; nt < 4; nt++)
#pragma unroll
            for (int q = 0; q < 4; q++) acc[mt][nt][q] = 0.f;

    // ---- load chunk 0 ----
    {
#pragma unroll
        for (int it = 0; it < 4; it++) {
            int idx = tid + it * 256;
            int row = idx >> 3, c4 = idx & 7;
            float4 v = *(const float4*)(x + (size_t)(m0 + row) * 128 + c4 * 4);
            *(uint2*)&AsH[0][row * 40 + c4 * 4] =
                make_uint2(f16x2(v.y, v.x), f16x2(v.w, v.z));
        }
#pragma unroll
        for (int it = 0; it < 2; it++) {
            int idx = tid + it * 256;
            int row = idx >> 3, c4 = idx & 7;
            *(uint2*)&BsH[0][row * 40 + c4 * 4] =
                *(const uint2*)&g_wh[(n0 + row) * 128 + c4 * 4];
        }
    }
    __syncthreads();

    for (int c = 0; c < 4; c++) {
        const int cur = c & 1;
        float4 xa[4];
        uint2 wb[2];
        if (c < 3) {
            const int kc = (c + 1) * 32;
#pragma unroll
            for (int it = 0; it < 4; it++) {
                int idx = tid + it * 256;
                int row = idx >> 3, c4 = idx & 7;
                xa[it] = *(const float4*)(x + (size_t)(m0 + row) * 128 + kc + c4 * 4);
            }
#pragma unroll
            for (int it = 0; it < 2; it++) {
                int idx = tid + it * 256;
                int row = idx >> 3, c4 = idx & 7;
                wb[it] = *(const uint2*)&g_wh[(n0 + row) * 128 + kc + c4 * 4];
            }
        }

        const uint32_t aB = aHb0 + cur * ABUF;
        const uint32_t bB = bHb0 + cur * BBUF;
#pragma unroll
        for (int ks = 0; ks < 2; ks++) {
            const uint32_t ko = ks * 32;
            uint32_t ah[2][4];
            ldsm4(ah[0], aB + ko);
            ldsm4(ah[1], aB + 1280 + ko);
            uint32_t bhp[2][4];
            ldsm4(bhp[0], bB + ko);
            ldsm4(bhp[1], bB + 1280 + ko);
#pragma unroll
            for (int mt = 0; mt < 2; mt++)
#pragma unroll
                for (int nt = 0; nt < 4; nt++) {
                    const int p = nt >> 1, off = (nt & 1) * 2;
                    mma16n8k16f16(acc[mt][nt], ah[mt], &bhp[p][off], acc[mt][nt]);
                }
        }

        if (c < 3) {
            const int nxt = cur ^ 1;
#pragma unroll
            for (int it = 0; it < 4; it++) {
                int idx = tid + it * 256;
                int row = idx >> 3, c4 = idx & 7;
                *(uint2*)&AsH[nxt][row * 40 + c4 * 4] =
                    make_uint2(f16x2(xa[it].y, xa[it].x), f16x2(xa[it].w, xa[it].z));
            }
#pragma unroll
            for (int it = 0; it < 2; it++) {
                int idx = tid + it * 256;
                int row = idx >> 3, c4 = idx & 7;
                *(uint2*)&BsH[nxt][row * 40 + c4 * 4] = wb[it];
            }
        }
        __syncthreads();
    }

    // Epilogue: fp16 stores to q (scaled), k, or v (transposed).
#pragma unroll
    for (int nt = 0; nt < 4; nt++) {
#pragma unroll
        for (int ei = 0; ei < 2; ei++) {
            const int e = n0 + wn * 32 + nt * 8 + 2 * t + ei;
            const float be = bias[e];
            const int h = e / 48, rc = e % 48;
            const int dd = rc & 15;
#pragma unroll
            for (int mt = 0; mt < 2; mt++) {
#pragma unroll
                for (int ri = 0; ri < 2; ri++) {
                    const int row = m0 + wm * 32 + mt * 16 + g + ri * 8;
                    const float val = acc[mt][nt][ri * 2 + ei] + be;
                    const int b_ = row >> 10, s_ = row & 1023;
                    const size_t bh_ = (size_t)(b_ * 8 + h);
                    if (rc < 16)
                        g_q16[(bh_ * 1024 + s_) * 16 + dd] = __float2half(val * L2E);
                    else if (rc < 32)
                        g_k16[(bh_ * 1024 + s_) * 16 + dd] = __float2half(val);
                    else
                        g_v16[(bh_ * 16 + dd) * 1024 + s_] = __float2half(val);
                }
            }
        }
    }
}

// ============================================================================
// Kernel 2: fp16 HMMA flash attention. QK^T fp16-accum -> ex2 direct;
// l via HADD2 ks-fold (2 ones-MMA / 32 keys). 64-key double-buffered chunks
// (16 iterations, 1 sync each). K smem [key][40]; V smem [d][72] (keys along
// row, source g_v16 is [d][s] transposed).
// ============================================================================
__global__ void __launch_bounds__(256) attn_kernel(float* __restrict__ out_attn)
{
    __shared__ __align__(16) __half Kh[2][64 * 40];
    __shared__ __align__(16) __half Vh[2][16 * 72];

    const int tid = threadIdx.x;
    const int lane = tid & 31;
    const int wid = tid >> 5;
    const int g = lane >> 2, t = lane & 3;
    const int m = lane >> 3, r = lane & 7;
    const int bh = blockIdx.y;
    const int q0 = blockIdx.x * 256 + wid * 32;
    const size_t base = (size_t)bh * S * DH;
    const __half* qb = g_q16 + base;
    const __half* kb = g_k16 + base;
    const __half* vt = g_v16 + base;   // [d][s]

    const uint32_t kLane = (((m >> 1) * 8 + r) * 40 + (m & 1) * 8) * 2;
    const uint32_t vLane = (((m >> 1) * 8 + r) * 72 + (m & 1) * 8) * 2;
    const uint32_t Kb[2] = { smem_u32(Kh[0]) + kLane, smem_u32(Kh[1]) + kLane };
    const uint32_t Vb[2] = { smem_u32(Vh[0]) + vLane, smem_u32(Vh[1]) + vLane };

    // Q fragments: direct 4B loads (already x log2e)
    uint32_t aq[2][4];
#pragma unroll
    for (int mt = 0; mt < 2; mt++) {
        const __half* qr0 = qb + (size_t)(q0 + mt * 16 + g) * 16;
        const __half* qr1 = qr0 + 8 * 16;
        aq[mt][0] = *(const uint32_t*)(qr0 + 2 * t);
        aq[mt][1] = *(const uint32_t*)(qr1 + 2 * t);
        aq[mt][2] = *(const uint32_t*)(qr0 + 8 + 2 * t);
        aq[mt][3] = *(const uint32_t*)(qr1 + 8 + 2 * t);
    }

    // ones B-fragment (l-sum in col n=0)
    const uint32_t bo = (g == 0) ? 0x3C003C00u : 0u;
    uint32_t bones[2];
    bones[0] = bo;
    bones[1] = bo;

    // cooperative loader indices (pure uint32 copies), 64-key chunk:
    // K: 64 rows x 8 u32 -> 2 items/thread
    // V: 16 rows x 32 u32 -> 2 items/thread
    const int ck0 = tid >> 2,  kc0 = (tid & 3) * 2;       // K item 0: rows 0..63
    const int kc1 = kc0 + 8;                              // K item 1: same row, cols+8
    const int dv0 = tid >> 4;                             // V rows 0..15
    const int kp0 = (tid & 15) * 2;                       // keys 0..30
    const int kp1 = kp0 + 32;                             // keys 32..62

    uint32_t kr0 = *(const uint32_t*)(kb + (size_t)ck0 * 16 + kc0);
    uint32_t kr1 = *(const uint32_t*)(kb + (size_t)ck0 * 16 + kc1);
    uint32_t vr0 = *(const uint32_t*)(vt + (size_t)dv0 * 1024 + kp0);
    uint32_t vr1 = *(const uint32_t*)(vt + (size_t)dv0 * 1024 + kp1);
    *(uint32_t*)&Kh[0][ck0 * 40 + kc0] = kr0;
    *(uint32_t*)&Kh[0][ck0 * 40 + kc1] = kr1;
    *(uint32_t*)&Vh[0][dv0 * 72 + kp0] = vr0;
    *(uint32_t*)&Vh[0][dv0 * 72 + kp1] = vr1;
    __syncthreads();

    float oa[2][2][4];
    float oL[2][4];
#pragma unroll
    for (int mt = 0; mt < 2; mt++) {
#pragma unroll
        for (int dt = 0; dt < 2; dt++)
#pragma unroll
            for (int q = 0; q < 4; q++) oa[mt][dt][q] = 0.f;
#pragma unroll
        for (int q = 0; q < 4; q++) oL[mt][q] = 0.f;
    }

    for (int ch = 0; ch < 16; ch++) {
        const int cur = ch & 1;

        if (ch < 15) {
            const size_t kg = (size_t)(ch + 1) * 64 * 16;
            kr0 = *(const uint32_t*)(kb + kg + (size_t)ck0 * 16 + kc0);
            kr1 = *(const uint32_t*)(kb + kg + (size_t)ck0 * 16 + kc1);
            vr0 = *(const uint32_t*)(vt + (size_t)dv0 * 1024 + (ch + 1) * 64 + kp0);
            vr1 = *(const uint32_t*)(vt + (size_t)dv0 * 1024 + (ch + 1) * 64 + kp1);
        }

#pragma unroll
        for (int hh = 0; hh < 2; hh++) {        // two 32-key halves
            // K fragments
            uint32_t kA0[4], kA1[4];
            ldsm4(kA0, Kb[cur] + hh * 2560);
            ldsm4(kA1, Kb[cur] + hh * 2560 + 1280);

            // S = Q K^T fp16-accum -> exp2 -> fp16 P A-fragments
            uint32_t ap[2][2][4];
#pragma unroll
            for (int j = 0; j < 4; j++) {
                const uint32_t* bk = (j < 2) ? &kA0[(j & 1) * 2] : &kA1[(j & 1) * 2];
#pragma unroll
                for (int mt = 0; mt < 2; mt++) {
                    uint32_t d2[2];
                    mma16n8k16h_z(d2, aq[mt], bk);
                    ap[mt][j >> 1][(j & 1) * 2 + 0] = h2ex2(d2[0]);
                    ap[mt][j >> 1][(j & 1) * 2 + 1] = h2ex2(d2[1]);
                }
            }

            // V fragments
            uint32_t vA0[4], vA1[4];
            ldsm4(vA0, Vb[cur] + hh * 64);
            ldsm4(vA1, Vb[cur] + hh * 64 + 32);

            // l += P: HADD2 ks-fold, one ones-MMA per mt
#pragma unroll
            for (int mt = 0; mt < 2; mt++) {
                uint32_t asum[4];
#pragma unroll
                for (int q = 0; q < 4; q++)
                    asum[q] = hadd2u(ap[mt][0][q], ap[mt][1][q]);
                mma16n8k16f16(oL[mt], asum, bones, oL[mt]);
            }

            // O += P V (f32 accum)
#pragma unroll
            for (int ks = 0; ks < 2; ks++) {
                const uint32_t* vfr = ks ? vA1 : vA0;
#pragma unroll
                for (int dt = 0; dt < 2; dt++)
#pragma unroll
                    for (int mt = 0; mt < 2; mt++)
                        mma16n8k16f16(oa[mt][dt], ap[mt][ks], &vfr[dt * 2], oa[mt][dt]);
            }
        }

        if (ch < 15) {
            const int nxt = cur ^ 1;
            *(uint32_t*)&Kh[nxt][ck0 * 40 + kc0] = kr0;
            *(uint32_t*)&Kh[nxt][ck0 * 40 + kc1] = kr1;
            *(uint32_t*)&Vh[nxt][dv0 * 72 + kp0] = vr0;
            *(uint32_t*)&Vh[nxt][dv0 * 72 + kp1] = vr1;
        }
        __syncthreads();
    }

    // l broadcast + normalize + write fp32 out_attn
#pragma unroll
    for (int mt = 0; mt < 2; mt++) {
        const float l0 = __shfl_sync(0xffffffffu, oL[mt][0], lane & ~3);
        const float l1 = __shfl_sync(0xffffffffu, oL[mt][2], lane & ~3);
        const float i0 = __fdividef(1.f, l0);
        const float i1 = __fdividef(1.f, l1);
        float* r0 = out_attn + base + (size_t)(q0 + mt * 16 + g) * 16;
        float* r1 = r0 + 8 * 16;
#pragma unroll
        for (int dt = 0; dt < 2; dt++) {
            r0[8 * dt + 2 * t]     = oa[mt][dt][0] * i0;
            r0[8 * dt + 2 * t + 1] = oa[mt][dt][1] * i0;
            r1[8 * dt + 2 * t]     = oa[mt][dt][2] * i1;
            r1[8 * dt + 2 * t + 1] = oa[mt][dt][3] * i1;
        }
    }
}

// ============================================================================
// Kernel 3: output projection, plain-fp16 HMMA + ldmatrix, DOUBLE-BUFFERED,
// 3 CTAs/SM. A cvt in-loader from fp32 out_attn; B from fp16 weights.
// ============================================================================
__global__ void __launch_bounds__(256, 3) proj_kernel(
    const float* __restrict__ attn, const float* __restrict__ bias,
    float* __restrict__ o)
{
    __shared__ __align__(16) __half AsH[2][128 * 40];
    __shared__ __align__(16) __half BsH[2][64 * 40];
    const int tid = threadIdx.x;
    const int lane = tid & 31;
    const int wid = tid >> 5;
    const int g = lane >> 2, t = lane & 3;
    const int m = lane >> 3, r = lane & 7;
    const int wm = wid & 3;
    const int wn = wid >> 2;
    const int m0 = blockIdx.x * 128;
    const int n0 = blockIdx.y * 64;

    const uint32_t aLane = ((wm * 32 + (m & 1) * 8 + r) * 40 + (m >> 1) * 8) * 2;
    const uint32_t bLane = ((wn * 32 + (m >> 1) * 8 + r) * 40 + (m & 1) * 8) * 2;
    const uint32_t aHb0 = smem_u32(AsH[0]) + aLane;
    const uint32_t bHb0 = smem_u32(BsH[0]) + bLane;
    const uint32_t ABUF = 128 * 40 * 2;
    const uint32_t BBUF = 64 * 40 * 2;

    float acc[2][4][4];
#pragma unroll
    for (int mt = 0; mt < 2; mt++)
#pragma unroll
        for (int nt = 0; nt < 4; nt++)
#pragma unroll
            for (int q = 0; q < 4; q++) acc[mt][nt][q] = 0.f;

    auto a_index = [&](int row, int c4, int kc) -> size_t {
        int gm = m0 + row;
        int b_ = gm >> 10, s_ = gm & 1023;
        int d0 = kc + c4 * 4;
        int h = d0 >> 4, dd = d0 & 15;
        return (((size_t)(b_ * 8 + h) << 10) + s_) * 16 + dd;
    };

    // ---- load chunk 0 ----
    {
#pragma unroll
        for (int it = 0; it < 4; it++) {
            int idx = tid + it * 256;
            int row = idx >> 3, c4 = idx & 7;
            float4 v = *(const float4*)(attn + a_index(row, c4, 0));
            *(uint2*)&AsH[0][row * 40 + c4 * 4] =
                make_uint2(f16x2(v.y, v.x), f16x2(v.w, v.z));
        }
#pragma unroll
        for (int it = 0; it < 2; it++) {
            int idx = tid + it * 256;
            int row = idx >> 3, c4 = idx & 7;
            *(uint2*)&BsH[0][row * 40 + c4 * 4] =
                *(const uint2*)&g_wh[WQKV_N + (n0 + row) * 128 + c4 * 4];
        }
    }
    __syncthreads();

    for (int c = 0; c < 4; c++) {
        const int cur = c & 1;
        float4 xa[4];
        uint2 wb[2];
        if (c < 3) {
            const int kc = (c + 1) * 32;
#pragma unroll
            for (int it = 0; it < 4; it++) {
                int idx = tid + it * 256;
                int row = idx >> 3, c4 = idx & 7;
                xa[it] = *(const float4*)(attn + a_index(row, c4, kc));
            }
#pragma unroll
            for (int it = 0; it < 2; it++) {
                int idx = tid + it * 256;
                int row = idx >> 3, c4 = idx & 7;
                wb[it] = *(const uint2*)&g_wh[WQKV_N + (n0 + row) * 128 + kc + c4 * 4];
            }
        }

        const uint32_t aB = aHb0 + cur * ABUF;
        const uint32_t bB = bHb0 + cur * BBUF;
#pragma unroll
        for (int ks = 0; ks < 2; ks++) {
            const uint32_t ko = ks * 32;
            uint32_t ah[2][4];
            ldsm4(ah[0], aB + ko);
            ldsm4(ah[1], aB + 1280 + ko);
            uint32_t bhp[2][4];
            ldsm4(bhp[0], bB + ko);
            ldsm4(bhp[1], bB + 1280 + ko);
#pragma unroll
            for (int mt = 0; mt < 2; mt++)
#pragma unroll
                for (int nt = 0; nt < 4; nt++) {
                    const int p = nt >> 1, off = (nt & 1) * 2;
                    mma16n8k16f16(acc[mt][nt], ah[mt], &bhp[p][off], acc[mt][nt]);
                }
        }

        if (c < 3) {
            const int nxt = cur ^ 1;
#pragma unroll
            for (int it = 0; it < 4; it++) {
                int idx = tid + it * 256;
                int row = idx >> 3, c4 = idx & 7;
                *(uint2*)&AsH[nxt][row * 40 + c4 * 4] =
                    make_uint2(f16x2(xa[it].y, xa[it].x), f16x2(xa[it].w, xa[it].z));
            }
#pragma unroll
            for (int it = 0; it < 2; it++) {
                int idx = tid + it * 256;
                int row = idx >> 3, c4 = idx & 7;
                *(uint2*)&BsH[nxt][row * 40 + c4 * 4] = wb[it];
            }
        }
        __syncthreads();
    }

#pragma unroll
    for (int nt = 0; nt < 4; nt++) {
        const int e0 = n0 + wn * 32 + nt * 8 + 2 * t;
        const int e1 = e0 + 1;
        const float be0 = bias[e0], be1 = bias[e1];
#pragma unroll
        for (int mt = 0; mt < 2; mt++) {
            const int ra = m0 + wm * 32 + mt * 16 + g;
            const int rb = ra + 8;
            o[(size_t)ra * 128 + e0] = acc[mt][nt][0] + be0;
            o[(size_t)ra * 128 + e1] = acc[mt][nt][1] + be1;
            o[(size_t)rb * 128 + e0] = acc[mt][nt][2] + be0;
            o[(size_t)rb * 128 + e1] = acc[mt][nt][3] + be1;
        }
    }
}

// ============================================================================
extern "C" void kernel_launch(void* const* d_in, const int* in_sizes, int n_in,
                              void* d_out, int out_size)
{
    const float* x    = (const float*)d_in[0];
    const float* Wqkv = (const float*)d_in[1];
    const float* bqkv = (const float*)d_in[2];
    const float* Wo   = (const float*)d_in[3];
    const float* bo   = (const float*)d_in[4];
    float* o    = (float*)d_out;
    float* attn = o + PER_T;  // outputs: o (b,s,128) then out_attn (b,h,s,16)

    prep_w<<<(WQKV_N + WO_N + 255) / 256, 256>>>(Wqkv, Wo);
    qkv_kernel<<<dim3(NTOK / 128, NQKV / 64), 256>>>(x, bqkv);
    attn_kernel<<<dim3(S / 256, B * H), 256>>>(attn);
    proj_kernel<<<dim3(NTOK / 128, DM / 64), 256>>>(attn, bo, o);
}